// round 1
// baseline (speedup 1.0000x reference)
#include <cuda_runtime.h>
#include <math.h>

#define N_NODES 50000
#define N_EDGES 800000
#define ET (N_EDGES + N_NODES)   // edges + self loops = 850000
#define F_IN 128
#define H 256
#define G_GRAPHS 500
#define FC1 196
#define D_OUT 10
#define NEG 0.2f

// ---------------- scratch (static device globals; no allocation) ----------------
__device__ float    g_featA[(size_t)N_NODES * H];   // GEMM output h = in @ W
__device__ float    g_featB[(size_t)N_NODES * H];   // aggregated output / next-layer input
__device__ float    g_as[N_NODES];                  // h . a_src per node
__device__ float    g_ad[N_NODES];                  // h . a_dst per node
__device__ unsigned g_maxkey[N_NODES];              // monotonic-encoded segment max
__device__ float    g_sum[N_NODES];                 // softmax denominator per dst
__device__ float    g_e[ET];                        // per-edge e, then exp(e-m)
__device__ float    g_hg[G_GRAPHS * H];             // pooled per-graph sums
__device__ float    g_cnt[G_GRAPHS];                // nodes per graph
__device__ float    g_fc1[G_GRAPHS * FC1];          // fc1 activations

// ---------------- helpers ----------------
__device__ __forceinline__ unsigned fkey(float f) {
    unsigned b = __float_as_uint(f);
    return (b & 0x80000000u) ? ~b : (b | 0x80000000u);
}
__device__ __forceinline__ float funkey(unsigned k) {
    return __uint_as_float((k & 0x80000000u) ? (k ^ 0x80000000u) : ~k);
}

// ---------------- GEMM: C[M,Nc] = A[M,K] @ W[K,Nc], K,Nc multiples of 32 ----------------
__global__ void gemm32(const float* __restrict__ A, const float* __restrict__ W,
                       float* __restrict__ C, int M, int K, int Nc) {
    __shared__ float sA[32][33];
    __shared__ float sB[32][33];
    int row = blockIdx.y * 32 + threadIdx.y;
    int col = blockIdx.x * 32 + threadIdx.x;
    float acc = 0.f;
    for (int k0 = 0; k0 < K; k0 += 32) {
        sA[threadIdx.y][threadIdx.x] = (row < M) ? A[(size_t)row * K + k0 + threadIdx.x] : 0.f;
        sB[threadIdx.y][threadIdx.x] = W[(size_t)(k0 + threadIdx.y) * Nc + col];
        __syncthreads();
#pragma unroll
        for (int kk = 0; kk < 32; kk++)
            acc += sA[threadIdx.y][kk] * sB[kk][threadIdx.x];
        __syncthreads();
    }
    if (row < M) C[(size_t)row * Nc + col] = acc;
}

// ---------------- per-node attention dots: as[i]=h[i].a_s, ad[i]=h[i].a_d ----------------
__global__ void node_dots(const float* __restrict__ a_s, const float* __restrict__ a_d) {
    int warp = (blockIdx.x * blockDim.x + threadIdx.x) >> 5;
    int lane = threadIdx.x & 31;
    if (warp >= N_NODES) return;
    const float* hr = g_featA + (size_t)warp * H;
    float s = 0.f, d = 0.f;
#pragma unroll
    for (int f = lane; f < H; f += 32) {
        float v = hr[f];
        s += v * a_s[f];
        d += v * a_d[f];
    }
#pragma unroll
    for (int o = 16; o; o >>= 1) {
        s += __shfl_down_sync(0xFFFFFFFFu, s, o);
        d += __shfl_down_sync(0xFFFFFFFFu, d, o);
    }
    if (lane == 0) { g_as[warp] = s; g_ad[warp] = d; }
}

// ---------------- zero featB, softmax accumulators ----------------
__global__ void init_layer() {
    int i = blockIdx.x * blockDim.x + threadIdx.x;
    int stride = gridDim.x * blockDim.x;
    for (size_t j = i; j < (size_t)N_NODES * H; j += stride) g_featB[j] = 0.f;
    for (int j = i; j < N_NODES; j += stride) { g_sum[j] = 0.f; g_maxkey[j] = 0u; }
}

// ---------------- edge pass A: e = lrelu(as[s]+ad[d]); segment max over dst ----------------
__global__ void edge_max(const int* __restrict__ ei) {
    int e = blockIdx.x * blockDim.x + threadIdx.x;
    if (e >= ET) return;
    int s, d;
    if (e < N_EDGES) { s = ei[e]; d = ei[N_EDGES + e]; }
    else             { s = d = e - N_EDGES; }
    float v = g_as[s] + g_ad[d];
    v = (v > 0.f) ? v : NEG * v;
    g_e[e] = v;
    atomicMax(&g_maxkey[d], fkey(v));
}

// ---------------- edge pass B: ex = exp(e - m[d]); segment sum over dst ----------------
__global__ void edge_exp(const int* __restrict__ ei) {
    int e = blockIdx.x * blockDim.x + threadIdx.x;
    if (e >= ET) return;
    int d = (e < N_EDGES) ? ei[N_EDGES + e] : (e - N_EDGES);
    float m = funkey(g_maxkey[d]);
    float ex = expf(g_e[e] - m);
    g_e[e] = ex;
    atomicAdd(&g_sum[d], ex);
}

// ---------------- edge pass C: out[d] += alpha * h[s]  (warp per edge) ----------------
__global__ void edge_agg(const int* __restrict__ ei) {
    int warp = (blockIdx.x * blockDim.x + threadIdx.x) >> 5;
    int lane = threadIdx.x & 31;
    if (warp >= ET) return;
    int s, d;
    if (warp < N_EDGES) { s = ei[warp]; d = ei[N_EDGES + warp]; }
    else                { s = d = warp - N_EDGES; }
    float alpha = g_e[warp] / fmaxf(g_sum[d], 1e-16f);
    const float* hs = g_featA + (size_t)s * H;
    float* od = g_featB + (size_t)d * H;
#pragma unroll
    for (int f = lane; f < H; f += 32)
        atomicAdd(&od[f], alpha * hs[f]);
}

// ---------------- bias + relu on featB ----------------
__global__ void bias_relu(const float* __restrict__ b) {
    size_t i = (size_t)blockIdx.x * blockDim.x + threadIdx.x;
    if (i >= (size_t)N_NODES * H) return;
    g_featB[i] = fmaxf(g_featB[i] + b[i & (H - 1)], 0.f);
}

// ---------------- pooling ----------------
__global__ void pool_init() {
    int i = blockIdx.x * blockDim.x + threadIdx.x;
    if (i < G_GRAPHS * H) g_hg[i] = 0.f;
    if (i < G_GRAPHS) g_cnt[i] = 0.f;
}

__global__ void pool(const int* __restrict__ batch) {
    int warp = (blockIdx.x * blockDim.x + threadIdx.x) >> 5;
    int lane = threadIdx.x & 31;
    if (warp >= N_NODES) return;
    int g = batch[warp];
    if (lane == 0) atomicAdd(&g_cnt[g], 1.f);
    const float* hr = g_featB + (size_t)warp * H;
#pragma unroll
    for (int f = lane; f < H; f += 32)
        atomicAdd(&g_hg[(size_t)g * H + f], hr[f]);
}

// ---------------- fc1: per-graph mean -> relu(hg @ fc1_w + b) ----------------
__global__ void fc1_kernel(const float* __restrict__ w, const float* __restrict__ b) {
    __shared__ float sh[H];
    int g = blockIdx.x;
    float c = fmaxf(g_cnt[g], 1.f);
    sh[threadIdx.x] = g_hg[(size_t)g * H + threadIdx.x] / c;
    __syncthreads();
    int j = threadIdx.x;
    if (j < FC1) {
        float acc = b[j];
#pragma unroll 8
        for (int k = 0; k < H; k++)
            acc += sh[k] * w[(size_t)k * FC1 + j];
        g_fc1[(size_t)g * FC1 + j] = fmaxf(acc, 0.f);
    }
}

// ---------------- fc2 ----------------
__global__ void fc2_kernel(const float* __restrict__ w, const float* __restrict__ b,
                           float* __restrict__ out) {
    int g = blockIdx.x;
    int o = threadIdx.x;
    if (o >= D_OUT) return;
    float acc = b[o];
#pragma unroll 4
    for (int k = 0; k < FC1; k++)
        acc += g_fc1[(size_t)g * FC1 + k] * w[(size_t)k * D_OUT + o];
    out[(size_t)g * D_OUT + o] = acc;
}

// ---------------- host ----------------
extern "C" void kernel_launch(void* const* d_in, const int* in_sizes, int n_in,
                              void* d_out, int out_size) {
    const float* x     = (const float*)d_in[0];
    const int*   ei    = (const int*)d_in[1];
    const int*   batch = (const int*)d_in[2];
    const float* W1 = (const float*)d_in[3];
    const float* a1s = (const float*)d_in[4];
    const float* a1d = (const float*)d_in[5];
    const float* b1 = (const float*)d_in[6];
    const float* W2 = (const float*)d_in[7];
    const float* a2s = (const float*)d_in[8];
    const float* a2d = (const float*)d_in[9];
    const float* b2 = (const float*)d_in[10];
    const float* W3 = (const float*)d_in[11];
    const float* a3s = (const float*)d_in[12];
    const float* a3d = (const float*)d_in[13];
    const float* b3 = (const float*)d_in[14];
    const float* fc1_w = (const float*)d_in[15];
    const float* fc1_b = (const float*)d_in[16];
    const float* fc2_w = (const float*)d_in[17];
    const float* fc2_b = (const float*)d_in[18];

    float* featA = nullptr;
    float* featB = nullptr;
    cudaGetSymbolAddress((void**)&featA, g_featA);
    cudaGetSymbolAddress((void**)&featB, g_featB);

    dim3 gemmBlock(32, 32);
    dim3 gemmGrid(H / 32, (N_NODES + 31) / 32);
    int edgeBlocks1 = (ET + 255) / 256;                 // thread per edge
    int edgeBlocksW = ((size_t)ET * 32 + 255) / 256;    // warp per edge
    int nodeBlocksW = ((size_t)N_NODES * 32 + 255) / 256;

    // ---- layer 1 (input = x, K = F_IN) ----
    gemm32<<<gemmGrid, gemmBlock>>>(x, W1, featA, N_NODES, F_IN, H);
    node_dots<<<nodeBlocksW, 256>>>(a1s, a1d);
    init_layer<<<1024, 256>>>();
    edge_max<<<edgeBlocks1, 256>>>(ei);
    edge_exp<<<edgeBlocks1, 256>>>(ei);
    edge_agg<<<edgeBlocksW, 256>>>(ei);
    bias_relu<<<((size_t)N_NODES * H + 255) / 256, 256>>>(b1);

    // ---- layer 2 (input = featB, K = H) ----
    gemm32<<<gemmGrid, gemmBlock>>>(featB, W2, featA, N_NODES, H, H);
    node_dots<<<nodeBlocksW, 256>>>(a2s, a2d);
    init_layer<<<1024, 256>>>();
    edge_max<<<edgeBlocks1, 256>>>(ei);
    edge_exp<<<edgeBlocks1, 256>>>(ei);
    edge_agg<<<edgeBlocksW, 256>>>(ei);
    bias_relu<<<((size_t)N_NODES * H + 255) / 256, 256>>>(b2);

    // ---- layer 3 ----
    gemm32<<<gemmGrid, gemmBlock>>>(featB, W3, featA, N_NODES, H, H);
    node_dots<<<nodeBlocksW, 256>>>(a3s, a3d);
    init_layer<<<1024, 256>>>();
    edge_max<<<edgeBlocks1, 256>>>(ei);
    edge_exp<<<edgeBlocks1, 256>>>(ei);
    edge_agg<<<edgeBlocksW, 256>>>(ei);
    bias_relu<<<((size_t)N_NODES * H + 255) / 256, 256>>>(b3);

    // ---- pooling + MLP head ----
    pool_init<<<(G_GRAPHS * H + 255) / 256, 256>>>();
    pool<<<nodeBlocksW, 256>>>(batch);
    fc1_kernel<<<G_GRAPHS, H>>>(fc1_w, fc1_b);
    fc2_kernel<<<G_GRAPHS, 32>>>(fc2_w, fc2_b, (float*)d_out);
}

// round 2
// speedup vs baseline: 3.7958x; 3.7958x over previous
#include <cuda_runtime.h>
#include <math.h>

#define N_NODES 50000
#define N_EDGES 800000
#define ET (N_EDGES + N_NODES)   // edges + self loops = 850000
#define F_IN 128
#define H 256
#define G_GRAPHS 500
#define FC1 196
#define D_OUT 10
#define NEG 0.2f

// ---------------- scratch (static device globals; no allocation) ----------------
__device__ float g_featA[(size_t)N_NODES * H];   // GEMM output h = in @ W
__device__ float g_featB[(size_t)N_NODES * H];   // aggregated output / next-layer input
__device__ float g_as[N_NODES];                  // h . a_src per node
__device__ float g_ad[N_NODES];                  // h . a_dst per node
__device__ float g_e[ET];                        // per-edge exp(e - m) (CSR order)
__device__ int   g_deg[N_NODES];                 // in-degree
__device__ int   g_off[N_NODES + 1];             // CSR row offsets (by dst)
__device__ int   g_pos[N_NODES];                 // scatter cursors
__device__ int   g_srcs[ET];                     // CSR column indices (src node)
__device__ float g_hg[G_GRAPHS * H];             // pooled per-graph sums
__device__ float g_cnt[G_GRAPHS];                // nodes per graph
__device__ float g_fc1[G_GRAPHS * FC1];          // fc1 activations

// ================= CSR build (per launch; deterministic structure) =================
__global__ void zero_deg() {
    int i = blockIdx.x * blockDim.x + threadIdx.x;
    if (i < N_NODES) g_deg[i] = 0;
}

__global__ void count_deg(const int* __restrict__ ei) {
    int e = blockIdx.x * blockDim.x + threadIdx.x;
    if (e >= ET) return;
    int d = (e < N_EDGES) ? ei[N_EDGES + e] : (e - N_EDGES);
    atomicAdd(&g_deg[d], 1);
}

// single-block exclusive scan of g_deg -> g_off, g_pos
__global__ void scan_deg() {
    __shared__ int warpsums[32];
    __shared__ int s_carry;
    int tid = threadIdx.x, lane = tid & 31, wid = tid >> 5;
    if (tid == 0) s_carry = 0;
    __syncthreads();
    for (int base = 0; base < N_NODES; base += 1024) {
        int i = base + tid;
        int v = (i < N_NODES) ? g_deg[i] : 0;
        int incl = v;
#pragma unroll
        for (int o = 1; o < 32; o <<= 1) {
            int t = __shfl_up_sync(0xFFFFFFFFu, incl, o);
            if (lane >= o) incl += t;
        }
        if (lane == 31) warpsums[wid] = incl;
        __syncthreads();
        if (wid == 0) {
            int w = warpsums[lane];
#pragma unroll
            for (int o = 1; o < 32; o <<= 1) {
                int t = __shfl_up_sync(0xFFFFFFFFu, w, o);
                if (lane >= o) w += t;
            }
            warpsums[lane] = w;
        }
        __syncthreads();
        int wofs = (wid > 0) ? warpsums[wid - 1] : 0;
        int excl = s_carry + wofs + incl - v;
        if (i < N_NODES) { g_off[i] = excl; g_pos[i] = excl; }
        __syncthreads();
        if (tid == 0) s_carry += warpsums[31];
        __syncthreads();
    }
    if (tid == 0) g_off[N_NODES] = ET;
}

__global__ void scatter_edges(const int* __restrict__ ei) {
    int e = blockIdx.x * blockDim.x + threadIdx.x;
    if (e >= ET) return;
    int s, d;
    if (e < N_EDGES) { s = ei[e]; d = ei[N_EDGES + e]; }
    else             { s = d = e - N_EDGES; }
    int idx = atomicAdd(&g_pos[d], 1);
    g_srcs[idx] = s;
}

// ================= register-tiled SGEMM: C[M,256] = A[M,K] @ W[K,256] =================
// 128x128 block tile, 256 threads, 8x8 per thread, BK=8
__global__ __launch_bounds__(256) void sgemm(const float* __restrict__ A,
                                             const float* __restrict__ W,
                                             float* __restrict__ C, int M, int K) {
    __shared__ float As[8][128];
    __shared__ float Bs[8][128];
    int tid  = threadIdx.x;
    int row0 = blockIdx.y * 128;
    int col0 = blockIdx.x * 128;
    int arow = tid >> 1;          // 0..127
    int acol = (tid & 1) * 4;     // 0 or 4
    int brow = tid >> 5;          // 0..7
    int bcol = (tid & 31) * 4;    // 0..124
    int ty = tid >> 4, tx = tid & 15;
    float acc[8][8] = {};
    int gr_a = row0 + arow;
    for (int k0 = 0; k0 < K; k0 += 8) {
        float4 av = make_float4(0.f, 0.f, 0.f, 0.f);
        if (gr_a < M) av = *(const float4*)(A + (size_t)gr_a * K + k0 + acol);
        As[acol + 0][arow] = av.x;
        As[acol + 1][arow] = av.y;
        As[acol + 2][arow] = av.z;
        As[acol + 3][arow] = av.w;
        *(float4*)&Bs[brow][bcol] = *(const float4*)(W + (size_t)(k0 + brow) * 256 + col0 + bcol);
        __syncthreads();
#pragma unroll
        for (int k = 0; k < 8; k++) {
            float ar[8], br[8];
#pragma unroll
            for (int i = 0; i < 8; i++) ar[i] = As[k][ty * 8 + i];
#pragma unroll
            for (int j = 0; j < 8; j++) br[j] = Bs[k][tx * 8 + j];
#pragma unroll
            for (int i = 0; i < 8; i++)
#pragma unroll
                for (int j = 0; j < 8; j++) acc[i][j] += ar[i] * br[j];
        }
        __syncthreads();
    }
#pragma unroll
    for (int i = 0; i < 8; i++) {
        int gr = row0 + ty * 8 + i;
        if (gr < M) {
            float4* cp = (float4*)(C + (size_t)gr * 256 + col0 + tx * 8);
            cp[0] = make_float4(acc[i][0], acc[i][1], acc[i][2], acc[i][3]);
            cp[1] = make_float4(acc[i][4], acc[i][5], acc[i][6], acc[i][7]);
        }
    }
}

// ================= per-node attention dots =================
__global__ void node_dots(const float* __restrict__ a_s, const float* __restrict__ a_d) {
    int warp = (blockIdx.x * blockDim.x + threadIdx.x) >> 5;
    int lane = threadIdx.x & 31;
    if (warp >= N_NODES) return;
    const float4* hr = (const float4*)(g_featA + (size_t)warp * H);
    float4 v0 = hr[lane], v1 = hr[lane + 32];
    const float4* asp = (const float4*)a_s;
    const float4* adp = (const float4*)a_d;
    float4 s0 = asp[lane], s1 = asp[lane + 32];
    float4 d0 = adp[lane], d1 = adp[lane + 32];
    float s = v0.x * s0.x + v0.y * s0.y + v0.z * s0.z + v0.w * s0.w
            + v1.x * s1.x + v1.y * s1.y + v1.z * s1.z + v1.w * s1.w;
    float d = v0.x * d0.x + v0.y * d0.y + v0.z * d0.z + v0.w * d0.w
            + v1.x * d1.x + v1.y * d1.y + v1.z * d1.z + v1.w * d1.w;
#pragma unroll
    for (int o = 16; o; o >>= 1) {
        s += __shfl_down_sync(0xFFFFFFFFu, s, o);
        d += __shfl_down_sync(0xFFFFFFFFu, d, o);
    }
    if (lane == 0) { g_as[warp] = s; g_ad[warp] = d; }
}

// ================= fused softmax + aggregate + bias + relu (warp per dst) =================
__global__ void gat_attn(const float* __restrict__ bias) {
    int warp = (blockIdx.x * blockDim.x + threadIdx.x) >> 5;
    int lane = threadIdx.x & 31;
    if (warp >= N_NODES) return;
    int beg = g_off[warp], end = g_off[warp + 1];
    float ad = g_ad[warp];

    // pass 1: segment max
    float m = -3.4e38f;
    for (int i = beg + lane; i < end; i += 32) {
        float e = g_as[g_srcs[i]] + ad;
        e = (e > 0.f) ? e : NEG * e;
        m = fmaxf(m, e);
    }
#pragma unroll
    for (int o = 16; o; o >>= 1) m = fmaxf(m, __shfl_xor_sync(0xFFFFFFFFu, m, o));

    // pass 2: exp + denom (store numerators to g_e)
    float denom = 0.f;
    for (int i = beg + lane; i < end; i += 32) {
        float e = g_as[g_srcs[i]] + ad;
        e = (e > 0.f) ? e : NEG * e;
        float ex = expf(e - m);
        g_e[i] = ex;
        denom += ex;
    }
#pragma unroll
    for (int o = 16; o; o >>= 1) denom += __shfl_xor_sync(0xFFFFFFFFu, denom, o);
    float inv = 1.f / fmaxf(denom, 1e-16f);

    // pass 3: weighted gather
    float4 acc0 = make_float4(0.f, 0.f, 0.f, 0.f);
    float4 acc1 = make_float4(0.f, 0.f, 0.f, 0.f);
    for (int i0 = beg; i0 < end; i0 += 32) {
        int i = i0 + lane;
        float a = 0.f; int s = 0;
        if (i < end) { s = g_srcs[i]; a = g_e[i] * inv; }
        int cnt = min(32, end - i0);
        for (int j = 0; j < cnt; j++) {
            float aj = __shfl_sync(0xFFFFFFFFu, a, j);
            int   sj = __shfl_sync(0xFFFFFFFFu, s, j);
            const float4* hs = (const float4*)(g_featA + (size_t)sj * H);
            float4 v0 = hs[lane], v1 = hs[lane + 32];
            acc0.x += aj * v0.x; acc0.y += aj * v0.y; acc0.z += aj * v0.z; acc0.w += aj * v0.w;
            acc1.x += aj * v1.x; acc1.y += aj * v1.y; acc1.z += aj * v1.z; acc1.w += aj * v1.w;
        }
    }
    const float4* bp = (const float4*)bias;
    float4 b0 = bp[lane], b1 = bp[lane + 32];
    float4 o0, o1;
    o0.x = fmaxf(acc0.x + b0.x, 0.f); o0.y = fmaxf(acc0.y + b0.y, 0.f);
    o0.z = fmaxf(acc0.z + b0.z, 0.f); o0.w = fmaxf(acc0.w + b0.w, 0.f);
    o1.x = fmaxf(acc1.x + b1.x, 0.f); o1.y = fmaxf(acc1.y + b1.y, 0.f);
    o1.z = fmaxf(acc1.z + b1.z, 0.f); o1.w = fmaxf(acc1.w + b1.w, 0.f);
    float4* out = (float4*)(g_featB + (size_t)warp * H);
    out[lane] = o0;
    out[lane + 32] = o1;
}

// ================= pooling =================
__global__ void pool_init() {
    int i = blockIdx.x * blockDim.x + threadIdx.x;
    if (i < G_GRAPHS * H) g_hg[i] = 0.f;
    if (i < G_GRAPHS) g_cnt[i] = 0.f;
}

__global__ void pool(const int* __restrict__ batch) {
    int warp = (blockIdx.x * blockDim.x + threadIdx.x) >> 5;
    int lane = threadIdx.x & 31;
    if (warp >= N_NODES) return;
    int g = batch[warp];
    if (lane == 0) atomicAdd(&g_cnt[g], 1.f);
    const float* hr = g_featB + (size_t)warp * H;
#pragma unroll
    for (int f = lane; f < H; f += 32)
        atomicAdd(&g_hg[(size_t)g * H + f], hr[f]);
}

// ================= MLP head =================
__global__ void fc1_kernel(const float* __restrict__ w, const float* __restrict__ b) {
    __shared__ float sh[H];
    int g = blockIdx.x;
    float c = fmaxf(g_cnt[g], 1.f);
    sh[threadIdx.x] = g_hg[(size_t)g * H + threadIdx.x] / c;
    __syncthreads();
    int j = threadIdx.x;
    if (j < FC1) {
        float acc = b[j];
#pragma unroll 8
        for (int k = 0; k < H; k++)
            acc += sh[k] * w[(size_t)k * FC1 + j];
        g_fc1[(size_t)g * FC1 + j] = fmaxf(acc, 0.f);
    }
}

__global__ void fc2_kernel(const float* __restrict__ w, const float* __restrict__ b,
                           float* __restrict__ out) {
    int g = blockIdx.x;
    int o = threadIdx.x;
    if (o >= D_OUT) return;
    float acc = b[o];
#pragma unroll 4
    for (int k = 0; k < FC1; k++)
        acc += g_fc1[(size_t)g * FC1 + k] * w[(size_t)k * D_OUT + o];
    out[(size_t)g * D_OUT + o] = acc;
}

// ================= host =================
extern "C" void kernel_launch(void* const* d_in, const int* in_sizes, int n_in,
                              void* d_out, int out_size) {
    const float* x     = (const float*)d_in[0];
    const int*   ei    = (const int*)d_in[1];
    const int*   batch = (const int*)d_in[2];
    const float* W1 = (const float*)d_in[3];
    const float* a1s = (const float*)d_in[4];
    const float* a1d = (const float*)d_in[5];
    const float* b1 = (const float*)d_in[6];
    const float* W2 = (const float*)d_in[7];
    const float* a2s = (const float*)d_in[8];
    const float* a2d = (const float*)d_in[9];
    const float* b2 = (const float*)d_in[10];
    const float* W3 = (const float*)d_in[11];
    const float* a3s = (const float*)d_in[12];
    const float* a3d = (const float*)d_in[13];
    const float* b3 = (const float*)d_in[14];
    const float* fc1_w = (const float*)d_in[15];
    const float* fc1_b = (const float*)d_in[16];
    const float* fc2_w = (const float*)d_in[17];
    const float* fc2_b = (const float*)d_in[18];

    float* featA = nullptr;
    float* featB = nullptr;
    cudaGetSymbolAddress((void**)&featA, g_featA);
    cudaGetSymbolAddress((void**)&featB, g_featB);

    dim3 gemmBlock(256);
    dim3 gemmGrid(2, (N_NODES + 127) / 128);
    int edgeBlocks = (ET + 255) / 256;
    int nodeBlocksW = ((size_t)N_NODES * 32 + 255) / 256;

    // ---- CSR by dst (structure reused by all 3 layers) ----
    zero_deg<<<(N_NODES + 255) / 256, 256>>>();
    count_deg<<<edgeBlocks, 256>>>(ei);
    scan_deg<<<1, 1024>>>();
    scatter_edges<<<edgeBlocks, 256>>>(ei);

    // ---- layer 1 (input = x, K = F_IN) ----
    sgemm<<<gemmGrid, gemmBlock>>>(x, W1, featA, N_NODES, F_IN);
    node_dots<<<nodeBlocksW, 256>>>(a1s, a1d);
    gat_attn<<<nodeBlocksW, 256>>>(b1);

    // ---- layer 2 ----
    sgemm<<<gemmGrid, gemmBlock>>>(featB, W2, featA, N_NODES, H);
    node_dots<<<nodeBlocksW, 256>>>(a2s, a2d);
    gat_attn<<<nodeBlocksW, 256>>>(b2);

    // ---- layer 3 ----
    sgemm<<<gemmGrid, gemmBlock>>>(featB, W3, featA, N_NODES, H);
    node_dots<<<nodeBlocksW, 256>>>(a3s, a3d);
    gat_attn<<<nodeBlocksW, 256>>>(b3);

    // ---- pooling + MLP head ----
    pool_init<<<(G_GRAPHS * H + 255) / 256, 256>>>();
    pool<<<nodeBlocksW, 256>>>(batch);
    fc1_kernel<<<G_GRAPHS, H>>>(fc1_w, fc1_b);
    fc2_kernel<<<G_GRAPHS, 32>>>(fc2_w, fc2_b, (float*)d_out);
}

// round 4
// speedup vs baseline: 6.1975x; 1.6327x over previous
#include <cuda_runtime.h>
#include <cuda_fp16.h>
#include <math.h>

#define N_NODES 50000
#define N_EDGES 800000
#define ET (N_EDGES + N_NODES)   // edges + self loops = 850000
#define F_IN 128
#define H 256
#define G_GRAPHS 500
#define FC1 196
#define D_OUT 10
#define NEG 0.2f

// ---------------- scratch (static device globals; no allocation) ----------------
__device__ float g_featA[(size_t)N_NODES * H];   // GEMM output h = in @ W (fp32)
__device__ float g_featB[(size_t)N_NODES * H];   // aggregated output / next-layer input
__device__ __align__(16) __half g_featH[(size_t)N_NODES * H]; // fp16 copy of h for gather
__device__ float g_as[N_NODES];                  // h . a_src per node
__device__ float g_ad[N_NODES];                  // h . a_dst per node
__device__ float g_e[ET];                        // per-edge exp(e - m) (CSR order, slow path)
__device__ int   g_deg[N_NODES];                 // in-degree
__device__ int   g_off[N_NODES + 1];             // CSR row offsets (by dst)
__device__ int   g_pos[N_NODES];                 // scatter cursors
__device__ int   g_srcs[ET];                     // CSR column indices (src node)
__device__ float g_hg[G_GRAPHS * H];             // pooled per-graph sums
__device__ float g_cnt[G_GRAPHS];                // nodes per graph
__device__ float g_fc1[G_GRAPHS * FC1];          // fc1 activations

// ================= CSR build =================
__global__ void zero_deg() {
    int i = blockIdx.x * blockDim.x + threadIdx.x;
    if (i < N_NODES) g_deg[i] = 0;
}

__global__ void count_deg(const int* __restrict__ ei) {
    int e = blockIdx.x * blockDim.x + threadIdx.x;
    if (e >= ET) return;
    int d = (e < N_EDGES) ? ei[N_EDGES + e] : (e - N_EDGES);
    atomicAdd(&g_deg[d], 1);
}

__global__ void scan_deg() {
    __shared__ int warpsums[32];
    __shared__ int s_carry;
    int tid = threadIdx.x, lane = tid & 31, wid = tid >> 5;
    if (tid == 0) s_carry = 0;
    __syncthreads();
    for (int base = 0; base < N_NODES; base += 1024) {
        int i = base + tid;
        int v = (i < N_NODES) ? g_deg[i] : 0;
        int incl = v;
#pragma unroll
        for (int o = 1; o < 32; o <<= 1) {
            int t = __shfl_up_sync(0xFFFFFFFFu, incl, o);
            if (lane >= o) incl += t;
        }
        if (lane == 31) warpsums[wid] = incl;
        __syncthreads();
        if (wid == 0) {
            int w = warpsums[lane];
#pragma unroll
            for (int o = 1; o < 32; o <<= 1) {
                int t = __shfl_up_sync(0xFFFFFFFFu, w, o);
                if (lane >= o) w += t;
            }
            warpsums[lane] = w;
        }
        __syncthreads();
        int wofs = (wid > 0) ? warpsums[wid - 1] : 0;
        int excl = s_carry + wofs + incl - v;
        if (i < N_NODES) { g_off[i] = excl; g_pos[i] = excl; }
        __syncthreads();
        if (tid == 0) s_carry += warpsums[31];
        __syncthreads();
    }
    if (tid == 0) g_off[N_NODES] = ET;
}

__global__ void scatter_edges(const int* __restrict__ ei) {
    int e = blockIdx.x * blockDim.x + threadIdx.x;
    if (e >= ET) return;
    int s, d;
    if (e < N_EDGES) { s = ei[e]; d = ei[N_EDGES + e]; }
    else             { s = d = e - N_EDGES; }
    int idx = atomicAdd(&g_pos[d], 1);
    g_srcs[idx] = s;
}

// ================= TF32 tensor-core GEMM: C[M,256] = A[M,K] @ W[K,256] =================
// 128x128 CTA tile, 256 threads = 8 warps in 2(M)x4(N) grid, warp tile 64x32,
// mma.sync.m16n8k8 tf32. SMEM [k][coord] layout, stride 136 words (conflict-free frags).
__device__ __forceinline__ unsigned f2tf32(float f) {
    unsigned u;
    asm("cvt.rna.tf32.f32 %0, %1;" : "=r"(u) : "f"(f));
    return u;
}

__global__ __launch_bounds__(256) void sgemm_tc(const float* __restrict__ A,
                                                const float* __restrict__ W,
                                                float* __restrict__ C, int M, int K) {
    __shared__ float As[16][136];   // [k][m]
    __shared__ float Bs[16][136];   // [k][n]
    int tid = threadIdx.x;
    int wid = tid >> 5, lane = tid & 31;
    int grp = lane >> 2, t4 = lane & 3;
    int wm = wid >> 2, wn = wid & 3;             // warp grid 2x4
    int row0 = blockIdx.y * 128;
    int col0 = blockIdx.x * 128;

    int arow = tid >> 2;            // 0..63 (+64 for second load)
    int acol = (tid & 3) * 4;       // 0,4,8,12
    int krow = tid >> 5;            // 0..7 (+8)
    int bcol = (tid & 31) * 4;      // 0..124

    float acc[4][4][4] = {};

    for (int k0 = 0; k0 < K; k0 += 16) {
        // --- load A tile (transpose to [k][m], tf32-round) ---
#pragma unroll
        for (int h = 0; h < 2; h++) {
            int r = arow + h * 64;
            int gr = row0 + r;
            float4 av = make_float4(0.f, 0.f, 0.f, 0.f);
            if (gr < M) av = *(const float4*)(A + (size_t)gr * K + k0 + acol);
            As[acol + 0][r] = __uint_as_float(f2tf32(av.x));
            As[acol + 1][r] = __uint_as_float(f2tf32(av.y));
            As[acol + 2][r] = __uint_as_float(f2tf32(av.z));
            As[acol + 3][r] = __uint_as_float(f2tf32(av.w));
        }
        // --- load B tile ([k][n] natural, tf32-round) ---
#pragma unroll
        for (int h = 0; h < 2; h++) {
            int kr = krow + h * 8;
            float4 bv = *(const float4*)(W + (size_t)(k0 + kr) * 256 + col0 + bcol);
            Bs[kr][bcol + 0] = __uint_as_float(f2tf32(bv.x));
            Bs[kr][bcol + 1] = __uint_as_float(f2tf32(bv.y));
            Bs[kr][bcol + 2] = __uint_as_float(f2tf32(bv.z));
            Bs[kr][bcol + 3] = __uint_as_float(f2tf32(bv.w));
        }
        __syncthreads();
#pragma unroll
        for (int ks = 0; ks < 16; ks += 8) {
            unsigned b0[4], b1[4];
#pragma unroll
            for (int j = 0; j < 4; j++) {
                int n = wn * 32 + j * 8 + grp;
                b0[j] = __float_as_uint(Bs[ks + t4][n]);
                b1[j] = __float_as_uint(Bs[ks + t4 + 4][n]);
            }
#pragma unroll
            for (int i = 0; i < 4; i++) {
                int m = wm * 64 + i * 16 + grp;
                unsigned a0 = __float_as_uint(As[ks + t4][m]);
                unsigned a1 = __float_as_uint(As[ks + t4][m + 8]);
                unsigned a2 = __float_as_uint(As[ks + t4 + 4][m]);
                unsigned a3 = __float_as_uint(As[ks + t4 + 4][m + 8]);
#pragma unroll
                for (int j = 0; j < 4; j++) {
                    asm("mma.sync.aligned.m16n8k8.row.col.f32.tf32.tf32.f32 "
                        "{%0,%1,%2,%3}, {%4,%5,%6,%7}, {%8,%9}, {%0,%1,%2,%3};"
                        : "+f"(acc[i][j][0]), "+f"(acc[i][j][1]),
                          "+f"(acc[i][j][2]), "+f"(acc[i][j][3])
                        : "r"(a0), "r"(a1), "r"(a2), "r"(a3),
                          "r"(b0[j]), "r"(b1[j]));
                }
            }
        }
        __syncthreads();
    }
    // --- epilogue ---
#pragma unroll
    for (int i = 0; i < 4; i++) {
#pragma unroll
        for (int j = 0; j < 4; j++) {
            int row = row0 + wm * 64 + i * 16 + grp;
            int col = col0 + wn * 32 + j * 8 + t4 * 2;
            if (row < M)
                *(float2*)(C + (size_t)row * 256 + col) =
                    make_float2(acc[i][j][0], acc[i][j][1]);
            if (row + 8 < M)
                *(float2*)(C + (size_t)(row + 8) * 256 + col) =
                    make_float2(acc[i][j][2], acc[i][j][3]);
        }
    }
}

// ================= per-node attention dots + fp16 copy =================
__global__ void node_dots(const float* __restrict__ a_s, const float* __restrict__ a_d) {
    int warp = (blockIdx.x * blockDim.x + threadIdx.x) >> 5;
    int lane = threadIdx.x & 31;
    if (warp >= N_NODES) return;
    const float4* hr = (const float4*)(g_featA + (size_t)warp * H);
    float4 v0 = hr[lane], v1 = hr[lane + 32];
    const float4* asp = (const float4*)a_s;
    const float4* adp = (const float4*)a_d;
    float4 s0 = asp[lane], s1 = asp[lane + 32];
    float4 d0 = adp[lane], d1 = adp[lane + 32];
    float s = v0.x * s0.x + v0.y * s0.y + v0.z * s0.z + v0.w * s0.w
            + v1.x * s1.x + v1.y * s1.y + v1.z * s1.z + v1.w * s1.w;
    float d = v0.x * d0.x + v0.y * d0.y + v0.z * d0.z + v0.w * d0.w
            + v1.x * d1.x + v1.y * d1.y + v1.z * d1.z + v1.w * d1.w;
    // fp16 copy for the aggregation gather
    __half2* hh = (__half2*)(g_featH + (size_t)warp * H);
    hh[lane * 2 + 0] = __floats2half2_rn(v0.x, v0.y);
    hh[lane * 2 + 1] = __floats2half2_rn(v0.z, v0.w);
    hh[(lane + 32) * 2 + 0] = __floats2half2_rn(v1.x, v1.y);
    hh[(lane + 32) * 2 + 1] = __floats2half2_rn(v1.z, v1.w);
#pragma unroll
    for (int o = 16; o; o >>= 1) {
        s += __shfl_down_sync(0xFFFFFFFFu, s, o);
        d += __shfl_down_sync(0xFFFFFFFFu, d, o);
    }
    if (lane == 0) { g_as[warp] = s; g_ad[warp] = d; }
}

// ================= fused softmax + aggregate + bias + relu (warp per dst) =================
__device__ __forceinline__ void agg_edge(int sj, float aj, int lane, float acc[8]) {
    const uint4* hs = (const uint4*)(g_featH + (size_t)sj * H);
    uint4 q = hs[lane];
    const __half2* h2 = (const __half2*)&q;
#pragma unroll
    for (int c = 0; c < 4; c++) {
        float2 f = __half22float2(h2[c]);
        acc[c * 2 + 0] += aj * f.x;
        acc[c * 2 + 1] += aj * f.y;
    }
}

__global__ void gat_attn(const float* __restrict__ bias) {
    int warp = (blockIdx.x * blockDim.x + threadIdx.x) >> 5;
    int lane = threadIdx.x & 31;
    if (warp >= N_NODES) return;
    int beg = g_off[warp], end = g_off[warp + 1];
    int deg = end - beg;
    float ad = g_ad[warp];
    float acc[8] = {};

    if (deg <= 32) {
        // fast path: whole row fits one warp-sweep; keep e in registers
        bool valid = lane < deg;
        int s = valid ? g_srcs[beg + lane] : 0;
        float e = -3.4e38f;
        if (valid) {
            e = g_as[s] + ad;
            e = (e > 0.f) ? e : NEG * e;
        }
        float m = e;
#pragma unroll
        for (int o = 16; o; o >>= 1) m = fmaxf(m, __shfl_xor_sync(0xFFFFFFFFu, m, o));
        float ex = valid ? expf(e - m) : 0.f;
        float denom = ex;
#pragma unroll
        for (int o = 16; o; o >>= 1) denom += __shfl_xor_sync(0xFFFFFFFFu, denom, o);
        float a = ex / fmaxf(denom, 1e-16f);
        for (int j = 0; j < deg; j++) {
            float aj = __shfl_sync(0xFFFFFFFFu, a, j);
            int   sj = __shfl_sync(0xFFFFFFFFu, s, j);
            agg_edge(sj, aj, lane, acc);
        }
    } else {
        float m = -3.4e38f;
        for (int i = beg + lane; i < end; i += 32) {
            float e = g_as[g_srcs[i]] + ad;
            e = (e > 0.f) ? e : NEG * e;
            m = fmaxf(m, e);
        }
#pragma unroll
        for (int o = 16; o; o >>= 1) m = fmaxf(m, __shfl_xor_sync(0xFFFFFFFFu, m, o));
        float denom = 0.f;
        for (int i = beg + lane; i < end; i += 32) {
            float e = g_as[g_srcs[i]] + ad;
            e = (e > 0.f) ? e : NEG * e;
            float ex = expf(e - m);
            g_e[i] = ex;
            denom += ex;
        }
#pragma unroll
        for (int o = 16; o; o >>= 1) denom += __shfl_xor_sync(0xFFFFFFFFu, denom, o);
        float inv = 1.f / fmaxf(denom, 1e-16f);
        for (int i0 = beg; i0 < end; i0 += 32) {
            int i = i0 + lane;
            float a = 0.f; int s = 0;
            if (i < end) { s = g_srcs[i]; a = g_e[i] * inv; }
            int cnt = min(32, end - i0);
            for (int j = 0; j < cnt; j++) {
                float aj = __shfl_sync(0xFFFFFFFFu, a, j);
                int   sj = __shfl_sync(0xFFFFFFFFu, s, j);
                agg_edge(sj, aj, lane, acc);
            }
        }
    }

    // bias + relu; features lane*8 + c
    float* out = g_featB + (size_t)warp * H + lane * 8;
    const float* bp = bias + lane * 8;
    float4 o0, o1;
    o0.x = fmaxf(acc[0] + bp[0], 0.f); o0.y = fmaxf(acc[1] + bp[1], 0.f);
    o0.z = fmaxf(acc[2] + bp[2], 0.f); o0.w = fmaxf(acc[3] + bp[3], 0.f);
    o1.x = fmaxf(acc[4] + bp[4], 0.f); o1.y = fmaxf(acc[5] + bp[5], 0.f);
    o1.z = fmaxf(acc[6] + bp[6], 0.f); o1.w = fmaxf(acc[7] + bp[7], 0.f);
    *(float4*)out = o0;
    *(float4*)(out + 4) = o1;
}

// ================= pooling =================
__global__ void pool_init() {
    int i = blockIdx.x * blockDim.x + threadIdx.x;
    if (i < G_GRAPHS * H) g_hg[i] = 0.f;
    if (i < G_GRAPHS) g_cnt[i] = 0.f;
}

__global__ void pool(const int* __restrict__ batch) {
    int warp = (blockIdx.x * blockDim.x + threadIdx.x) >> 5;
    int lane = threadIdx.x & 31;
    if (warp >= N_NODES) return;
    int g = batch[warp];
    if (lane == 0) atomicAdd(&g_cnt[g], 1.f);
    const float* hr = g_featB + (size_t)warp * H;
#pragma unroll
    for (int f = lane; f < H; f += 32)
        atomicAdd(&g_hg[(size_t)g * H + f], hr[f]);
}

// ================= MLP head =================
__global__ void fc1_kernel(const float* __restrict__ w, const float* __restrict__ b) {
    __shared__ float sh[H];
    int g = blockIdx.x;
    float c = fmaxf(g_cnt[g], 1.f);
    sh[threadIdx.x] = g_hg[(size_t)g * H + threadIdx.x] / c;
    __syncthreads();
    int j = threadIdx.x;
    if (j < FC1) {
        float acc = b[j];
#pragma unroll 8
        for (int k = 0; k < H; k++)
            acc += sh[k] * w[(size_t)k * FC1 + j];
        g_fc1[(size_t)g * FC1 + j] = fmaxf(acc, 0.f);
    }
}

__global__ void fc2_kernel(const float* __restrict__ w, const float* __restrict__ b,
                           float* __restrict__ out) {
    int g = blockIdx.x;
    int o = threadIdx.x;
    if (o >= D_OUT) return;
    float acc = b[o];
#pragma unroll 4
    for (int k = 0; k < FC1; k++)
        acc += g_fc1[(size_t)g * FC1 + k] * w[(size_t)k * D_OUT + o];
    out[(size_t)g * D_OUT + o] = acc;
}

// ================= host =================
extern "C" void kernel_launch(void* const* d_in, const int* in_sizes, int n_in,
                              void* d_out, int out_size) {
    const float* x     = (const float*)d_in[0];
    const int*   ei    = (const int*)d_in[1];
    const int*   batch = (const int*)d_in[2];
    const float* W1 = (const float*)d_in[3];
    const float* a1s = (const float*)d_in[4];
    const float* a1d = (const float*)d_in[5];
    const float* b1 = (const float*)d_in[6];
    const float* W2 = (const float*)d_in[7];
    const float* a2s = (const float*)d_in[8];
    const float* a2d = (const float*)d_in[9];
    const float* b2 = (const float*)d_in[10];
    const float* W3 = (const float*)d_in[11];
    const float* a3s = (const float*)d_in[12];
    const float* a3d = (const float*)d_in[13];
    const float* b3 = (const float*)d_in[14];
    const float* fc1_w = (const float*)d_in[15];
    const float* fc1_b = (const float*)d_in[16];
    const float* fc2_w = (const float*)d_in[17];
    const float* fc2_b = (const float*)d_in[18];

    float* featA = nullptr;
    float* featB = nullptr;
    cudaGetSymbolAddress((void**)&featA, g_featA);
    cudaGetSymbolAddress((void**)&featB, g_featB);

    dim3 gemmGrid(2, (N_NODES + 127) / 128);
    int edgeBlocks = (ET + 255) / 256;
    int nodeBlocksW = ((size_t)N_NODES * 32 + 255) / 256;

    // ---- CSR by dst ----
    zero_deg<<<(N_NODES + 255) / 256, 256>>>();
    count_deg<<<edgeBlocks, 256>>>(ei);
    scan_deg<<<1, 1024>>>();
    scatter_edges<<<edgeBlocks, 256>>>(ei);

    // ---- layer 1 ----
    sgemm_tc<<<gemmGrid, 256>>>(x, W1, featA, N_NODES, F_IN);
    node_dots<<<nodeBlocksW, 256>>>(a1s, a1d);
    gat_attn<<<nodeBlocksW, 256>>>(b1);

    // ---- layer 2 ----
    sgemm_tc<<<gemmGrid, 256>>>(featB, W2, featA, N_NODES, H);
    node_dots<<<nodeBlocksW, 256>>>(a2s, a2d);
    gat_attn<<<nodeBlocksW, 256>>>(b2);

    // ---- layer 3 ----
    sgemm_tc<<<gemmGrid, 256>>>(featB, W3, featA, N_NODES, H);
    node_dots<<<nodeBlocksW, 256>>>(a3s, a3d);
    gat_attn<<<nodeBlocksW, 256>>>(b3);

    // ---- pooling + MLP head ----
    pool_init<<<(G_GRAPHS * H + 255) / 256, 256>>>();
    pool<<<nodeBlocksW, 256>>>(batch);
    fc1_kernel<<<G_GRAPHS, H>>>(fc1_w, fc1_b);
    fc2_kernel<<<G_GRAPHS, 32>>>(fc2_w, fc2_b, (float*)d_out);
}